// round 5
// baseline (speedup 1.0000x reference)
#include <cuda_runtime.h>
#include <math.h>
#include <stdint.h>

#define EPSF 1e-6f
#define NINPUT 64
#define NLAYER 63

// ---------------------------------------------------------------------------
// Persistent scratch (no allocations allowed)
// ---------------------------------------------------------------------------
__device__ __align__(16) float    g_lc[512];     // per-layer F constants (63*8 used)
__device__ __align__(16) uint32_t g_Pf[4096];    // tf32 P in mma-B fragment order

// ---------------------------------------------------------------------------
// helpers
// ---------------------------------------------------------------------------
__device__ __forceinline__ uint32_t tf32_rn(float f) {
    uint32_t u;
    asm("cvt.rna.tf32.f32 %0, %1;" : "=r"(u) : "f"(f));
    return u;
}
__device__ __forceinline__ float ex2(float t) {
    float r; asm("ex2.approx.ftz.f32 %0, %1;" : "=f"(r) : "f"(t)); return r;
}
__device__ __forceinline__ float lg2(float t) {
    float r; asm("lg2.approx.ftz.f32 %0, %1;" : "=f"(r) : "f"(t)); return r;
}
__device__ __forceinline__ float rcpf(float t) {
    float r; asm("rcp.approx.ftz.f32 %0, %1;" : "=f"(r) : "f"(t)); return r;
}
__device__ __forceinline__ void mma_tf32(float* d, uint32_t a0, uint32_t a1, uint32_t a2,
                                         uint32_t a3, uint32_t b0, uint32_t b1) {
    asm("mma.sync.aligned.m16n8k8.row.col.f32.tf32.tf32.f32 "
        "{%0,%1,%2,%3}, {%4,%5,%6,%7}, {%8,%9}, {%0,%1,%2,%3};"
        : "+f"(d[0]), "+f"(d[1]), "+f"(d[2]), "+f"(d[3])
        : "r"(a0), "r"(a1), "r"(a2), "r"(a3), "r"(b0), "r"(b1));
}

// ---------------------------------------------------------------------------
// Setup: LINEAR-space Sinkhorn (exp once, then sum+rcp scaling) + fragment-
// ordered tf32 P + per-layer F constants.
// ---------------------------------------------------------------------------
__global__ __launch_bounds__(1024) void setup_kernel(const float* __restrict__ logits,
                                                     const float* __restrict__ weights,
                                                     const float* __restrict__ biases)
{
    __shared__ float L[64][65];
    const int tid = threadIdx.x, w = tid >> 5, lane = tid & 31;

    for (int i = tid; i < 4096; i += 1024) L[i >> 6][i & 63] = __expf(logits[i]);
    __syncthreads();

    for (int it = 0; it < 20; ++it) {
        #pragma unroll
        for (int rr = 0; rr < 2; ++rr) {                // rows (axis=1)
            int r = w + rr * 32;
            float v0 = L[r][lane], v1 = L[r][lane + 32];
            float s = v0 + v1;
            #pragma unroll
            for (int o = 16; o; o >>= 1) s += __shfl_xor_sync(0xffffffffu, s, o);
            float inv = rcpf(s);
            L[r][lane] = v0 * inv; L[r][lane + 32] = v1 * inv;
        }
        __syncthreads();
        #pragma unroll
        for (int cc = 0; cc < 2; ++cc) {                // cols (axis=0)
            int c = w + cc * 32;
            float v0 = L[lane][c], v1 = L[lane + 32][c];
            float s = v0 + v1;
            #pragma unroll
            for (int o = 16; o; o >>= 1) s += __shfl_xor_sync(0xffffffffu, s, o);
            float inv = rcpf(s);
            L[lane][c] = v0 * inv; L[lane + 32][c] = v1 * inv;
        }
        __syncthreads();
    }

    // Fragment-ordered B: g_Pf[((kt*8+nt)*32 + lane)*2 + j] = tf32(P[kt*8+tg+4j][nt*8+g])
    //   (g = lane>>2, tg = lane&3) -- matches mma consumer exactly.
    for (int i = tid; i < 4096; i += 1024) {
        int j = i & 1, ln = (i >> 1) & 31, ntk = i >> 6;
        int nt = ntk & 7, kt = ntk >> 3;
        int g = ln >> 2, tg = ln & 3;
        int k = kt * 8 + tg + 4 * j, n = nt * 8 + g;
        g_Pf[i] = tf32_rn(L[k][n]);
    }

    // Per-layer constants: r = A + bw0*xc + bw1*yc + C * exp2(e0*log2(xs)+e1*log2(ys))
    //   xs = |off - xc| (off=0 -> xc ; off=1 -> 1-xc)
    if (tid < NLAYER) {
        float w0 = weights[tid], w1 = 1.0f - w0, a = biases[tid];
        float A, C, cl, e0 = 0.0f, e1 = 0.0f, off;
        if (fabsf(a - 0.5f) < EPSF) {
            A = 0.0f; cl = 1.0f; C = 0.0f; off = 0.0f;
        } else if (a < 0.5f) {
            float ar = fminf(fmaxf(1.0f - a, -1.0f + EPSF), 2.0f - EPSF);
            float p  = sqrtf(3.0f / fmaxf(2.0f - ar, EPSF)) - 1.0f;
            e0 = 2.0f * w0 * p; e1 = 2.0f * w1 * p;
            float bl, bg;
            if      (fabsf(ar - 2.0f) < EPSF) { bl = 0.0f; bg = 0.0f; }
            else if (ar >= 0.75f)             { bl = 0.0f; bg = 1.0f; }
            else if (ar > 0.5f)               { bl = 3.0f - 4.0f * ar; bg = 4.0f * ar - 2.0f; }
            else                              { bl = 1.0f; bg = 0.0f; }
            A = 1.0f - bl; cl = bl; C = -bg; off = 1.0f;
        } else {
            float p = sqrtf(3.0f / fmaxf(2.0f - a, EPSF)) - 1.0f;
            e0 = 2.0f * w0 * p; e1 = 2.0f * w1 * p;
            float bl, bg;
            if      (fabsf(a - 2.0f) < EPSF) { bl = 0.0f; bg = 0.0f; }
            else if (a >= 0.75f)             { bl = 0.0f; bg = 1.0f; }
            else if (a > 0.5f)               { bl = 3.0f - 4.0f * a; bg = 4.0f * a - 2.0f; }
            else                             { bl = 1.0f; bg = 0.0f; }
            A = 0.0f; cl = bl; C = bg; off = 0.0f;
        }
        float* lc = &g_lc[tid * 8];
        lc[0] = cl * w0; lc[1] = cl * w1; lc[2] = A;   lc[3] = C;
        lc[4] = e0;      lc[5] = e1;      lc[6] = off; lc[7] = a;
    }
}

// ---------------------------------------------------------------------------
// Main: 256 threads / CTA, 128 rows / CTA, 8 warps x 16 rows (1 m-tile each).
// B frags via coalesced LDG.64 from g_Pf (L1-shared across CTAs).
// SMEM = X tile only, aliased by SL after GEMM. Scan on threads 0-127.
//   X:  tf32 [128 r][68]   (4g+tg bank-injective for A frags)
//   SL: f32  [64 leaf][132] (8tg+g+16w injective epilogue; scan row-coalesced)
// ---------------------------------------------------------------------------
#define XS 68
#define LS 132
#define SM_SIZE (128 * XS * 4)   // 34816 B; SL needs 64*132*4 = 33792 <= this

__global__ __launch_bounds__(256, 3) void main_kernel(const float* __restrict__ x,
                                                      float* __restrict__ out,
                                                      int batch)
{
    extern __shared__ __align__(16) uint8_t smem[];
    uint32_t* sX  = reinterpret_cast<uint32_t*>(smem);
    float*    sSL = reinterpret_cast<float*>(smem);

    const int tid = threadIdx.x, w = tid >> 5, lane = tid & 31;
    const int g = lane >> 2, tg = lane & 3;

    // ---- stage X tile: 128 rows = 2048 float4 ----
    const size_t f4_limit = (size_t)batch * 16;
    const size_t f4_base  = (size_t)blockIdx.x * 2048;
    const float4* gx = reinterpret_cast<const float4*>(x);
    #pragma unroll
    for (int t = 0; t < 8; ++t) {
        int i = tid + t * 256;
        size_t gi = f4_base + i;
        float4 v = (gi < f4_limit) ? __ldcs(&gx[gi]) : make_float4(0.f, 0.f, 0.f, 0.f);
        uint4 u;
        u.x = tf32_rn(v.x); u.y = tf32_rn(v.y); u.z = tf32_rn(v.z); u.w = tf32_rn(v.w);
        int r = i >> 4, c = (i & 15) << 2;
        *reinterpret_cast<uint4*>(&sX[r * XS + c]) = u;
    }
    __syncthreads();

    // ---- GEMM: warp w computes rows [w*16, w*16+16) x 64 leaves ----
    float d[8][4];
    #pragma unroll
    for (int nt = 0; nt < 8; ++nt)
        #pragma unroll
        for (int e = 0; e < 4; ++e) d[nt][e] = 0.0f;

    const int r0 = w * 16 + g;
    const uint2* Pf2 = reinterpret_cast<const uint2*>(g_Pf);
    #pragma unroll
    for (int kt = 0; kt < 8; ++kt) {
        const int c0 = kt * 8 + tg;
        uint32_t a0 = sX[r0 * XS + c0];
        uint32_t a1 = sX[(r0 + 8) * XS + c0];
        uint32_t a2 = sX[r0 * XS + c0 + 4];
        uint32_t a3 = sX[(r0 + 8) * XS + c0 + 4];
        #pragma unroll
        for (int nt = 0; nt < 8; ++nt) {
            uint2 b = __ldg(&Pf2[(kt * 8 + nt) * 32 + lane]);
            mma_tf32(d[nt], a0, a1, a2, a3, b.x, b.y);
        }
    }
    __syncthreads();   // all warps done reading X before SL aliases it

    // ---- epilogue: D -> SL[leaf][row] (transposed, conflict-free) ----
    #pragma unroll
    for (int nt = 0; nt < 8; ++nt) {
        int c0 = nt * 8 + tg * 2;
        sSL[c0 * LS + r0]           = d[nt][0];
        sSL[(c0 + 1) * LS + r0]     = d[nt][1];
        sSL[c0 * LS + r0 + 8]       = d[nt][2];
        sSL[(c0 + 1) * LS + r0 + 8] = d[nt][3];
    }
    __syncthreads();

    // ---- 63-layer scan: threads 0-127 scan their row ----
    if (tid < 128) {
        const float4* lc4 = reinterpret_cast<const float4*>(g_lc);
        float state = sSL[tid];
        #pragma unroll
        for (int i = 0; i < NLAYER; ++i) {
            float leaf = sSL[(i + 1) * LS + tid];
            float4 c0 = __ldg(&lc4[i * 2]);
            float4 c1 = __ldg(&lc4[i * 2 + 1]);

            float xc = fminf(fmaxf(state, EPSF), 1.0f - EPSF);
            float yc = fminf(fmaxf(leaf,  EPSF), 1.0f - EPSF);
            float xs = fabsf(c1.z - xc);
            float ys = fabsf(c1.z - yc);
            float t  = fmaf(c1.x, lg2(xs), c1.y * lg2(ys));
            float gg = ex2(t);
            float r  = fmaf(c0.w, gg, fmaf(c0.y, yc, fmaf(c0.x, xc, c0.z)));
            state = isnan(r) ? c1.w : r;
        }

        int row = blockIdx.x * 128 + tid;
        if (row < batch) out[row] = state;
    }
}

// ---------------------------------------------------------------------------
// Launch
// ---------------------------------------------------------------------------
extern "C" void kernel_launch(void* const* d_in, const int* in_sizes, int n_in,
                              void* d_out, int out_size)
{
    const float* x       = (const float*)d_in[0];
    const float* logits  = (const float*)d_in[1];
    const float* weights = (const float*)d_in[2];
    const float* biases  = (const float*)d_in[3];
    float* out = (float*)d_out;

    int batch = in_sizes[0] / NINPUT;

    cudaFuncSetAttribute(main_kernel, cudaFuncAttributeMaxDynamicSharedMemorySize, SM_SIZE);

    setup_kernel<<<1, 1024>>>(logits, weights, biases);
    main_kernel<<<(batch + 127) / 128, 256, SM_SIZE>>>(x, out, batch);
}

// round 6
// speedup vs baseline: 1.2944x; 1.2944x over previous
#include <cuda_runtime.h>
#include <math.h>
#include <stdint.h>

#define EPSF 1e-6f
#define NINPUT 64
#define NLAYER 63

// ---------------------------------------------------------------------------
// Persistent scratch (no allocations allowed)
// ---------------------------------------------------------------------------
__device__ __align__(16) float    g_lc[512];     // per-layer F constants (63*8 used)
__device__ __align__(16) uint32_t g_Pf[4096];    // tf32 P in mma-B fragment order

// Layer constants in constant bank for the scan (copied from g_lc via D2D memcpy)
__constant__ float4 c_lc[NLAYER * 2];

// ---------------------------------------------------------------------------
// helpers
// ---------------------------------------------------------------------------
__device__ __forceinline__ uint32_t tf32_rn(float f) {
    uint32_t u;
    asm("cvt.rna.tf32.f32 %0, %1;" : "=r"(u) : "f"(f));
    return u;
}
__device__ __forceinline__ float ex2(float t) {
    float r; asm("ex2.approx.ftz.f32 %0, %1;" : "=f"(r) : "f"(t)); return r;
}
__device__ __forceinline__ float lg2(float t) {
    float r; asm("lg2.approx.ftz.f32 %0, %1;" : "=f"(r) : "f"(t)); return r;
}
__device__ __forceinline__ float rcpf(float t) {
    float r; asm("rcp.approx.ftz.f32 %0, %1;" : "=f"(r) : "f"(t)); return r;
}
__device__ __forceinline__ void mma_tf32(float* d, uint32_t a0, uint32_t a1, uint32_t a2,
                                         uint32_t a3, uint32_t b0, uint32_t b1) {
    asm("mma.sync.aligned.m16n8k8.row.col.f32.tf32.tf32.f32 "
        "{%0,%1,%2,%3}, {%4,%5,%6,%7}, {%8,%9}, {%0,%1,%2,%3};"
        : "+f"(d[0]), "+f"(d[1]), "+f"(d[2]), "+f"(d[3])
        : "r"(a0), "r"(a1), "r"(a2), "r"(a3), "r"(b0), "r"(b1));
}

// ---------------------------------------------------------------------------
// Setup: u/v-form Sinkhorn.  u = 1/(M v); v = 1/(M^T u); P = u (.) M (.) v.
// Both M and M^T kept row-contiguous in smem -> both matvecs are serial
// float4 dots per thread, no shuffle chains; 2 barriers per iteration.
// ---------------------------------------------------------------------------
__global__ __launch_bounds__(256) void setup_kernel(const float* __restrict__ logits,
                                                    const float* __restrict__ weights,
                                                    const float* __restrict__ biases)
{
    __shared__ __align__(16) float M[64 * 68];
    __shared__ __align__(16) float Mt[64 * 68];
    __shared__ __align__(16) float u[64], v[64];
    const int tid = threadIdx.x;

    for (int i = tid; i < 4096; i += 256) {
        int r = i >> 6, c = i & 63;
        float m = __expf(logits[i]);
        M[r * 68 + c]  = m;
        Mt[c * 68 + r] = m;
    }
    if (tid < 64) v[tid] = 1.0f;
    __syncthreads();

    for (int it = 0; it < 20; ++it) {
        if (tid < 64) {                       // u = 1/(M v)   (row normalize)
            const float4* mr = reinterpret_cast<const float4*>(&M[tid * 68]);
            const float4* vv = reinterpret_cast<const float4*>(v);
            float s = 0.0f;
            #pragma unroll
            for (int q = 0; q < 16; ++q) {
                float4 a = mr[q], b = vv[q];
                s += a.x * b.x + a.y * b.y + a.z * b.z + a.w * b.w;
            }
            u[tid] = rcpf(s);
        }
        __syncthreads();
        if (tid < 64) {                       // v = 1/(M^T u) (col normalize)
            const float4* mr = reinterpret_cast<const float4*>(&Mt[tid * 68]);
            const float4* uu = reinterpret_cast<const float4*>(u);
            float s = 0.0f;
            #pragma unroll
            for (int q = 0; q < 16; ++q) {
                float4 a = mr[q], b = uu[q];
                s += a.x * b.x + a.y * b.y + a.z * b.z + a.w * b.w;
            }
            v[tid] = rcpf(s);
        }
        __syncthreads();
    }

    // Fragment-ordered B: g_Pf[((kt*8+nt)*32 + lane)*2 + j] = tf32(P[kt*8+tg+4j][nt*8+g])
    //   (g = lane>>2, tg = lane&3) -- matches the mma consumer exactly (R5-verified).
    for (int i = tid; i < 4096; i += 256) {
        int j = i & 1, ln = (i >> 1) & 31, ntk = i >> 6;
        int nt = ntk & 7, kt = ntk >> 3;
        int g = ln >> 2, tg = ln & 3;
        int k = kt * 8 + tg + 4 * j, n = nt * 8 + g;
        g_Pf[i] = tf32_rn(u[k] * M[k * 68 + n] * v[n]);
    }

    // Per-layer constants: r = A + bw0*xc + bw1*yc + C * exp2(e0*log2(xs)+e1*log2(ys))
    //   xs = |off - xc| (off=0 -> xc ; off=1 -> 1-xc)
    if (tid < NLAYER) {
        float w0 = weights[tid], w1 = 1.0f - w0, a = biases[tid];
        float A, C, cl, e0 = 0.0f, e1 = 0.0f, off;
        if (fabsf(a - 0.5f) < EPSF) {
            A = 0.0f; cl = 1.0f; C = 0.0f; off = 0.0f;
        } else if (a < 0.5f) {
            float ar = fminf(fmaxf(1.0f - a, -1.0f + EPSF), 2.0f - EPSF);
            float p  = sqrtf(3.0f / fmaxf(2.0f - ar, EPSF)) - 1.0f;
            e0 = 2.0f * w0 * p; e1 = 2.0f * w1 * p;
            float bl, bg;
            if      (fabsf(ar - 2.0f) < EPSF) { bl = 0.0f; bg = 0.0f; }
            else if (ar >= 0.75f)             { bl = 0.0f; bg = 1.0f; }
            else if (ar > 0.5f)               { bl = 3.0f - 4.0f * ar; bg = 4.0f * ar - 2.0f; }
            else                              { bl = 1.0f; bg = 0.0f; }
            A = 1.0f - bl; cl = bl; C = -bg; off = 1.0f;
        } else {
            float p = sqrtf(3.0f / fmaxf(2.0f - a, EPSF)) - 1.0f;
            e0 = 2.0f * w0 * p; e1 = 2.0f * w1 * p;
            float bl, bg;
            if      (fabsf(a - 2.0f) < EPSF) { bl = 0.0f; bg = 0.0f; }
            else if (a >= 0.75f)             { bl = 0.0f; bg = 1.0f; }
            else if (a > 0.5f)               { bl = 3.0f - 4.0f * a; bg = 4.0f * a - 2.0f; }
            else                             { bl = 1.0f; bg = 0.0f; }
            A = 0.0f; cl = bl; C = bg; off = 0.0f;
        }
        float* lc = &g_lc[tid * 8];
        lc[0] = cl * w0; lc[1] = cl * w1; lc[2] = A;   lc[3] = C;
        lc[4] = e0;      lc[5] = e1;      lc[6] = off; lc[7] = a;
    }
}

// ---------------------------------------------------------------------------
// Main: 128 threads / CTA, 128 rows, 4 warps x 2 m-tiles (rows == threads, so
// EVERY thread scans). B frags via __ldg from g_Pf (L1-shared across CTAs).
// Layer consts from __constant__ (c-bank operands). SMEM = X tile only,
// aliased by SL after GEMM. 5 CTAs/SM -> 20 warps, all scan-active.
//   X:  tf32 [128 r][68]    (4g+tg bank-injective for A frags)
//   SL: f32  [64 leaf][132] (8tg+g bank-injective epilogue; scan row-coalesced)
// ---------------------------------------------------------------------------
#define XS 68
#define LS 132
#define SM_SIZE (128 * XS * 4)   // 34816 B; SL needs 64*132*4 = 33792 <= this

__global__ __launch_bounds__(128, 5) void main_kernel(const float* __restrict__ x,
                                                      float* __restrict__ out,
                                                      int batch)
{
    extern __shared__ __align__(16) uint8_t smem[];
    uint32_t* sX  = reinterpret_cast<uint32_t*>(smem);
    float*    sSL = reinterpret_cast<float*>(smem);

    const int tid = threadIdx.x, w = tid >> 5, lane = tid & 31;
    const int g = lane >> 2, tg = lane & 3;

    // ---- stage X tile: 128 rows = 2048 float4 ----
    const size_t f4_limit = (size_t)batch * 16;
    const size_t f4_base  = (size_t)blockIdx.x * 2048;
    const float4* gx = reinterpret_cast<const float4*>(x);
    #pragma unroll
    for (int t = 0; t < 16; ++t) {
        int i = tid + t * 128;
        size_t gi = f4_base + i;
        float4 v = (gi < f4_limit) ? __ldcs(&gx[gi]) : make_float4(0.f, 0.f, 0.f, 0.f);
        uint4 uv;
        uv.x = tf32_rn(v.x); uv.y = tf32_rn(v.y); uv.z = tf32_rn(v.z); uv.w = tf32_rn(v.w);
        int r = i >> 4, c = (i & 15) << 2;
        *reinterpret_cast<uint4*>(&sX[r * XS + c]) = uv;
    }
    __syncthreads();

    // ---- GEMM: warp w computes rows [w*32, w*32+32) x 64 leaves ----
    float d[2][8][4];
    #pragma unroll
    for (int mt = 0; mt < 2; ++mt)
        #pragma unroll
        for (int nt = 0; nt < 8; ++nt)
            #pragma unroll
            for (int e = 0; e < 4; ++e) d[mt][nt][e] = 0.0f;

    const int rb = w * 32 + g;
    const uint2* Pf2 = reinterpret_cast<const uint2*>(g_Pf);
    #pragma unroll
    for (int kt = 0; kt < 8; ++kt) {
        const int c0 = kt * 8 + tg;
        uint32_t a[2][4];
        #pragma unroll
        for (int mt = 0; mt < 2; ++mt) {
            int r0 = rb + mt * 16;
            a[mt][0] = sX[r0 * XS + c0];
            a[mt][1] = sX[(r0 + 8) * XS + c0];
            a[mt][2] = sX[r0 * XS + c0 + 4];
            a[mt][3] = sX[(r0 + 8) * XS + c0 + 4];
        }
        #pragma unroll
        for (int nt = 0; nt < 8; ++nt) {
            uint2 b = __ldg(&Pf2[(kt * 8 + nt) * 32 + lane]);
            mma_tf32(d[0][nt], a[0][0], a[0][1], a[0][2], a[0][3], b.x, b.y);
            mma_tf32(d[1][nt], a[1][0], a[1][1], a[1][2], a[1][3], b.x, b.y);
        }
    }
    __syncthreads();   // all warps done reading X before SL aliases it

    // ---- epilogue: D -> SL[leaf][row] (transposed, conflict-free) ----
    #pragma unroll
    for (int mt = 0; mt < 2; ++mt) {
        int r0 = w * 32 + mt * 16 + g;
        #pragma unroll
        for (int nt = 0; nt < 8; ++nt) {
            int c0 = nt * 8 + tg * 2;
            sSL[c0 * LS + r0]           = d[mt][nt][0];
            sSL[(c0 + 1) * LS + r0]     = d[mt][nt][1];
            sSL[c0 * LS + r0 + 8]       = d[mt][nt][2];
            sSL[(c0 + 1) * LS + r0 + 8] = d[mt][nt][3];
        }
    }
    __syncthreads();

    // ---- 63-layer scan: every thread scans its row; consts from c-bank ----
    // NaN fallback dropped: e0,e1 >= 0 and xs,ys >= EPSF => r is always finite.
    float state = sSL[tid];
    #pragma unroll
    for (int i = 0; i < NLAYER; ++i) {
        float leaf = sSL[(i + 1) * LS + tid];
        float4 k0 = c_lc[i * 2];
        float4 k1 = c_lc[i * 2 + 1];

        float xc = fminf(fmaxf(state, EPSF), 1.0f - EPSF);
        float yc = fminf(fmaxf(leaf,  EPSF), 1.0f - EPSF);
        float lgx = lg2(fabsf(k1.z - xc));
        float lgy = lg2(fabsf(k1.z - yc));
        float t  = fmaf(k1.x, lgx, k1.y * lgy);
        float gg = ex2(t);
        state = fmaf(k0.w, gg, fmaf(k0.y, yc, fmaf(k0.x, xc, k0.z)));
    }

    int row = blockIdx.x * 128 + tid;
    if (row < batch) out[row] = state;
}

// ---------------------------------------------------------------------------
// Launch
// ---------------------------------------------------------------------------
extern "C" void kernel_launch(void* const* d_in, const int* in_sizes, int n_in,
                              void* d_out, int out_size)
{
    const float* x       = (const float*)d_in[0];
    const float* logits  = (const float*)d_in[1];
    const float* weights = (const float*)d_in[2];
    const float* biases  = (const float*)d_in[3];
    float* out = (float*)d_out;

    int batch = in_sizes[0] / NINPUT;

    cudaFuncSetAttribute(main_kernel, cudaFuncAttributeMaxDynamicSharedMemorySize, SM_SIZE);

    setup_kernel<<<1, 256>>>(logits, weights, biases);

    // layer consts -> constant bank (D2D async copy; graph-capturable)
    void* lc_dev = nullptr;
    cudaGetSymbolAddress(&lc_dev, g_lc);
    cudaMemcpyToSymbolAsync(c_lc, lc_dev, NLAYER * 8 * sizeof(float), 0,
                            cudaMemcpyDeviceToDevice, 0);

    main_kernel<<<(batch + 127) / 128, 128, SM_SIZE>>>(x, out, batch);
}